// round 3
// baseline (speedup 1.0000x reference)
#include <cuda_runtime.h>

// x: [8, 64, 64, 64, 64] fp32. Per (b,c) slice of 64^3:
//   s = sum over 2x2x2 windows of (max(window) + mean(window))
//   pooled[b,c] = s^2 ;  out[b,c] = pooled / max(||pooled[b,:]||_2, 1e-12)
//
// 2048 blocks = 512 slices x 4 h2-chunks (fine grain -> short tail, ~6
// resident blocks/SM). Fused finalize in the last block (atomic ticket).

#define CH 4
#define NBC 512
#define NBLK (NBC * CH)   // 2048

__device__ float g_partial[NBLK];
__device__ unsigned int g_counter = 0;

__global__ __launch_bounds__(256) void fused_pool_kernel(const float* __restrict__ x,
                                                         float* __restrict__ out) {
    const int bc    = blockIdx.x >> 2;
    const int chunk = blockIdx.x & 3;
    const float* __restrict__ base = x + (size_t)bc * (64 * 64 * 64);

    const int tid = threadIdx.x;       // 256 threads
    const int tx  = tid & 15;          // d-group: d = 4*tx .. 4*tx+3 (two d2 windows)
    const int g   = tid >> 4;          // 0..15: strides over (h2, w2) pairs

    float acc = 0.0f;

    // 256 (h2,w2) pairs in this chunk: h2 in [chunk*8, chunk*8+8), w2 in [0,32)
    #pragma unroll 4
    for (int p = g; p < 256; p += 16) {
        const int h2 = (chunk << 3) + (p >> 5);
        const int w2 = p & 31;
        const float* r = base + ((size_t)(2 * h2) * 4096) + ((2 * w2) * 64) + (tx << 2);

        const float4 a = __ldcs((const float4*)(r));              // (2h2,   2w2  )
        const float4 b = __ldcs((const float4*)(r + 64));         // (2h2,   2w2+1)
        const float4 c = __ldcs((const float4*)(r + 4096));       // (2h2+1, 2w2  )
        const float4 d = __ldcs((const float4*)(r + 4096 + 64));  // (2h2+1, 2w2+1)

        float m0 = fmaxf(fmaxf(fmaxf(a.x, a.y), fmaxf(b.x, b.y)),
                         fmaxf(fmaxf(c.x, c.y), fmaxf(d.x, d.y)));
        float m1 = fmaxf(fmaxf(fmaxf(a.z, a.w), fmaxf(b.z, b.w)),
                         fmaxf(fmaxf(c.z, c.w), fmaxf(d.z, d.w)));

        float sum = (a.x + a.y + a.z + a.w) + (b.x + b.y + b.z + b.w)
                  + (c.x + c.y + c.z + c.w) + (d.x + d.y + d.z + d.w);

        acc += m0 + m1 + sum * 0.125f;
    }

    // block reduce: warp shuffle then smem across 8 warps
    __shared__ float swarp[8];
    __shared__ int s_islast;
    #pragma unroll
    for (int off = 16; off > 0; off >>= 1)
        acc += __shfl_xor_sync(0xFFFFFFFFu, acc, off);
    if ((tid & 31) == 0) swarp[tid >> 5] = acc;
    __syncthreads();

    if (tid == 0) {
        float t = swarp[0] + swarp[1] + swarp[2] + swarp[3]
                + swarp[4] + swarp[5] + swarp[6] + swarp[7];
        g_partial[blockIdx.x] = t;
        __threadfence();                          // publish before ticket
        unsigned int old = atomicAdd(&g_counter, 1u);
        s_islast = (old == (unsigned int)(gridDim.x - 1));
    }
    __syncthreads();
    if (!s_islast) return;

    // ---- last block: finalize (all 2048 partials visible) ----
    __threadfence();
    __shared__ float s_norm[8];

    const int w = tid >> 5;            // warp 0..7 -> batch b
    const int l = tid & 31;            // lane -> channels l and l+32

    const int i0 = (w * 64 + l) * CH;
    const int i1 = (w * 64 + l + 32) * CH;
    const float s0 = g_partial[i0] + g_partial[i0 + 1] + g_partial[i0 + 2] + g_partial[i0 + 3];
    const float s1 = g_partial[i1] + g_partial[i1 + 1] + g_partial[i1 + 2] + g_partial[i1 + 3];
    const float p0 = s0 * s0;
    const float p1 = s1 * s1;

    float q = p0 * p0 + p1 * p1;
    #pragma unroll
    for (int off = 16; off > 0; off >>= 1)
        q += __shfl_xor_sync(0xFFFFFFFFu, q, off);

    if (l == 0) s_norm[w] = fmaxf(sqrtf(q), 1e-12f);
    __syncthreads();

    const float inv = 1.0f / s_norm[w];
    out[w * 64 + l]      = p0 * inv;
    out[w * 64 + l + 32] = p1 * inv;

    if (tid == 0) g_counter = 0;       // reset for next graph replay
}

extern "C" void kernel_launch(void* const* d_in, const int* in_sizes, int n_in,
                              void* d_out, int out_size) {
    const float* x = (const float*)d_in[0];
    float* out = (float*)d_out;
    fused_pool_kernel<<<NBLK, 256>>>(x, out);
}

// round 4
// speedup vs baseline: 1.0487x; 1.0487x over previous
#include <cuda_runtime.h>

// x: [8, 64, 64, 64, 64] fp32. Per (b,c) slice of 64^3:
//   s = sum over 2x2x2 windows of (max(window) + mean(window))
//   pooled[b,c] = s^2 ;  out[b,c] = pooled / max(||pooled[b,:]||_2, 1e-12)
//
// 2048 blocks = 512 slices x 4 h2-chunks (fine grain -> short tail).
// Plain LDG.128 (no .cs — measured 5% DRAM-throughput loss from evict-stream
// hint in R3). Fused finalize in the last block (atomic ticket).

#define CH 4
#define NBC 512
#define NBLK (NBC * CH)   // 2048

__device__ float g_partial[NBLK];
__device__ unsigned int g_counter = 0;

__global__ __launch_bounds__(256) void fused_pool_kernel(const float* __restrict__ x,
                                                         float* __restrict__ out) {
    const int bc    = blockIdx.x >> 2;
    const int chunk = blockIdx.x & 3;
    const float* __restrict__ base = x + (size_t)bc * (64 * 64 * 64);

    const int tid = threadIdx.x;       // 256 threads
    const int tx  = tid & 15;          // d-group: d = 4*tx .. 4*tx+3 (two d2 windows)
    const int g   = tid >> 4;          // 0..15: strides over (h2, w2) pairs

    float acc = 0.0f;

    // 256 (h2,w2) pairs in this chunk: h2 in [chunk*8, chunk*8+8), w2 in [0,32)
    #pragma unroll 4
    for (int p = g; p < 256; p += 16) {
        const int h2 = (chunk << 3) + (p >> 5);
        const int w2 = p & 31;
        const float* r = base + ((size_t)(2 * h2) * 4096) + ((2 * w2) * 64) + (tx << 2);

        const float4 a = *(const float4*)(r);                 // (2h2,   2w2  )
        const float4 b = *(const float4*)(r + 64);            // (2h2,   2w2+1)
        const float4 c = *(const float4*)(r + 4096);          // (2h2+1, 2w2  )
        const float4 d = *(const float4*)(r + 4096 + 64);     // (2h2+1, 2w2+1)

        float m0 = fmaxf(fmaxf(fmaxf(a.x, a.y), fmaxf(b.x, b.y)),
                         fmaxf(fmaxf(c.x, c.y), fmaxf(d.x, d.y)));
        float m1 = fmaxf(fmaxf(fmaxf(a.z, a.w), fmaxf(b.z, b.w)),
                         fmaxf(fmaxf(c.z, c.w), fmaxf(d.z, d.w)));

        float sum = (a.x + a.y + a.z + a.w) + (b.x + b.y + b.z + b.w)
                  + (c.x + c.y + c.z + c.w) + (d.x + d.y + d.z + d.w);

        acc += m0 + m1 + sum * 0.125f;
    }

    // block reduce: warp shuffle then smem across 8 warps
    __shared__ float swarp[8];
    __shared__ int s_islast;
    #pragma unroll
    for (int off = 16; off > 0; off >>= 1)
        acc += __shfl_xor_sync(0xFFFFFFFFu, acc, off);
    if ((tid & 31) == 0) swarp[tid >> 5] = acc;
    __syncthreads();

    if (tid == 0) {
        float t = swarp[0] + swarp[1] + swarp[2] + swarp[3]
                + swarp[4] + swarp[5] + swarp[6] + swarp[7];
        g_partial[blockIdx.x] = t;
        __threadfence();                          // publish before ticket
        unsigned int old = atomicAdd(&g_counter, 1u);
        s_islast = (old == (unsigned int)(gridDim.x - 1));
    }
    __syncthreads();
    if (!s_islast) return;

    // ---- last block: finalize (all 2048 partials visible) ----
    __threadfence();
    __shared__ float s_norm[8];

    const int w = tid >> 5;            // warp 0..7 -> batch b
    const int l = tid & 31;            // lane -> channels l and l+32

    const int i0 = (w * 64 + l) * CH;
    const int i1 = (w * 64 + l + 32) * CH;
    const float s0 = g_partial[i0] + g_partial[i0 + 1] + g_partial[i0 + 2] + g_partial[i0 + 3];
    const float s1 = g_partial[i1] + g_partial[i1 + 1] + g_partial[i1 + 2] + g_partial[i1 + 3];
    const float p0 = s0 * s0;
    const float p1 = s1 * s1;

    float q = p0 * p0 + p1 * p1;
    #pragma unroll
    for (int off = 16; off > 0; off >>= 1)
        q += __shfl_xor_sync(0xFFFFFFFFu, q, off);

    if (l == 0) s_norm[w] = fmaxf(sqrtf(q), 1e-12f);
    __syncthreads();

    const float inv = 1.0f / s_norm[w];
    out[w * 64 + l]      = p0 * inv;
    out[w * 64 + l + 32] = p1 * inv;

    if (tid == 0) g_counter = 0;       // reset for next graph replay
}

extern "C" void kernel_launch(void* const* d_in, const int* in_sizes, int n_in,
                              void* d_out, int out_size) {
    const float* x = (const float*)d_in[0];
    float* out = (float*)d_out;
    fused_pool_kernel<<<NBLK, 256>>>(x, out);
}

// round 5
// speedup vs baseline: 1.1054x; 1.0541x over previous
#include <cuda_runtime.h>

// x: [8, 64, 64, 64, 64] fp32. Per (b,c) slice of 64^3:
//   s = sum over 2x2x2 windows of (max(window) + mean(window))
//   pooled[b,c] = s^2 ;  out[b,c] = pooled / max(||pooled[b,:]||_2, 1e-12)
//
// 1024 blocks = 512 slices x 2 half-slices (512 KB each): keeps the
// low-CTA-count regime that measured the best DRAM% (R2), with 4x finer
// tail granularity. Plain LDG.128. Fused last-block finalize.

#define CH 2
#define NBC 512
#define NBLK (NBC * CH)   // 1024

__device__ float g_partial[NBLK];
__device__ unsigned int g_counter = 0;

__global__ __launch_bounds__(256) void fused_pool_kernel(const float* __restrict__ x,
                                                         float* __restrict__ out) {
    const int bc    = blockIdx.x >> 1;
    const int half  = blockIdx.x & 1;

    const int tid = threadIdx.x;       // 256 threads
    const int tx  = tid & 15;          // d-group: d = 4*tx..4*tx+3 (two d2 windows)
    const int g   = tid >> 4;          // 0..15: w2 start; strides w2 by 16

    // start: h2 = half*16, w2 = g, d = 4*tx
    const float* r0 = x + (size_t)bc * (64 * 64 * 64)
                        + ((size_t)(half * 32) * 4096) + (2 * g * 64) + (tx << 2);

    float acc = 0.0f;

    #pragma unroll 2
    for (int h2i = 0; h2i < 16; h2i++) {          // 16 h2 rows in this half
        const float* r = r0;
        #pragma unroll
        for (int w2i = 0; w2i < 2; w2i++) {       // w2 = g, g+16
            const float4 a = *(const float4*)(r);                 // (2h2,   2w2  )
            const float4 b = *(const float4*)(r + 64);            // (2h2,   2w2+1)
            const float4 c = *(const float4*)(r + 4096);          // (2h2+1, 2w2  )
            const float4 d = *(const float4*)(r + 4096 + 64);     // (2h2+1, 2w2+1)

            float m0 = fmaxf(fmaxf(fmaxf(a.x, a.y), fmaxf(b.x, b.y)),
                             fmaxf(fmaxf(c.x, c.y), fmaxf(d.x, d.y)));
            float m1 = fmaxf(fmaxf(fmaxf(a.z, a.w), fmaxf(b.z, b.w)),
                             fmaxf(fmaxf(c.z, c.w), fmaxf(d.z, d.w)));

            float sum = (a.x + a.y + a.z + a.w) + (b.x + b.y + b.z + b.w)
                      + (c.x + c.y + c.z + c.w) + (d.x + d.y + d.z + d.w);

            acc += m0 + m1 + sum * 0.125f;
            r += 2 * 16 * 64;                     // w2 += 16
        }
        r0 += 2 * 4096;                           // h2 += 1
    }

    // block reduce: warp shuffle then smem across 8 warps
    __shared__ float swarp[8];
    __shared__ int s_islast;
    #pragma unroll
    for (int off = 16; off > 0; off >>= 1)
        acc += __shfl_xor_sync(0xFFFFFFFFu, acc, off);
    if ((tid & 31) == 0) swarp[tid >> 5] = acc;
    __syncthreads();

    if (tid == 0) {
        float t = swarp[0] + swarp[1] + swarp[2] + swarp[3]
                + swarp[4] + swarp[5] + swarp[6] + swarp[7];
        g_partial[blockIdx.x] = t;
        __threadfence();                          // publish before ticket
        unsigned int old = atomicAdd(&g_counter, 1u);
        s_islast = (old == (unsigned int)(gridDim.x - 1));
    }
    __syncthreads();
    if (!s_islast) return;

    // ---- last block: finalize (all 1024 partials visible) ----
    __threadfence();
    __shared__ float s_norm[8];

    const int w = tid >> 5;            // warp 0..7 -> batch b
    const int l = tid & 31;            // lane -> channels l and l+32

    const int i0 = (w * 64 + l) * CH;
    const int i1 = (w * 64 + l + 32) * CH;
    const float s0 = g_partial[i0] + g_partial[i0 + 1];
    const float s1 = g_partial[i1] + g_partial[i1 + 1];
    const float p0 = s0 * s0;
    const float p1 = s1 * s1;

    float q = p0 * p0 + p1 * p1;
    #pragma unroll
    for (int off = 16; off > 0; off >>= 1)
        q += __shfl_xor_sync(0xFFFFFFFFu, q, off);

    if (l == 0) s_norm[w] = fmaxf(sqrtf(q), 1e-12f);
    __syncthreads();

    const float inv = 1.0f / s_norm[w];
    out[w * 64 + l]      = p0 * inv;
    out[w * 64 + l + 32] = p1 * inv;

    if (tid == 0) g_counter = 0;       // reset for next graph replay
}

extern "C" void kernel_launch(void* const* d_in, const int* in_sizes, int n_in,
                              void* d_out, int out_size) {
    const float* x = (const float*)d_in[0];
    float* out = (float*)d_out;
    fused_pool_kernel<<<NBLK, 256>>>(x, out);
}